// round 4
// baseline (speedup 1.0000x reference)
#include <cuda_runtime.h>
#include <cuda_fp16.h>
#include <cstdint>

#define D_MODEL 1024
#define NE 64
#define NN 128
#define BM 128
#define BK 32               // fp32 K per chunk
#define NCH (D_MODEL / BK)  // 32
#define ASTG 3
#define BSTG 4
#define ABYTES 16384        // per A stage: 2 splits x (128 rows x 64B)
#define BBYTES 16384        // per B stage: 2 splits x (32 rows x 256B)
#define SM_B_OFF (ASTG * ABYTES)                 // 49152
#define SMEM_BYTES (SM_B_OFF + BSTG * BBYTES)    // 114688
#define CSTRIDE 130

// pre-split, pre-swizzled weights: [chunk][split] 8KB images
__device__ __align__(128) unsigned char g_Bf[NCH * 2 * 8192];

__device__ __forceinline__ uint32_t smem_u32(const void* p) {
    uint32_t a;
    asm("{ .reg .u64 t; cvta.to.shared.u64 t, %1; cvt.u32.u64 %0, t; }" : "=r"(a) : "l"(p));
    return a;
}
#define CP16(dst, src) asm volatile("cp.async.ca.shared.global [%0], [%1], 16;" :: "r"(dst), "l"(src))
#define CP_COMMIT()    asm volatile("cp.async.commit_group;")

#define LDSM4(r, p) \
    asm volatile("ldmatrix.sync.aligned.m8n8.x4.shared.b16 {%0,%1,%2,%3}, [%4];" \
                 : "=r"((r)[0]), "=r"((r)[1]), "=r"((r)[2]), "=r"((r)[3]) : "r"(p))
#define LDSM4T(r, p) \
    asm volatile("ldmatrix.sync.aligned.m8n8.x4.trans.shared.b16 {%0,%1,%2,%3}, [%4];" \
                 : "=r"((r)[0]), "=r"((r)[1]), "=r"((r)[2]), "=r"((r)[3]) : "r"(p))
#define MMA16816(d, a, b0, b1) \
    asm volatile("mma.sync.aligned.m16n8k16.row.col.f32.f16.f16.f32 " \
                 "{%0,%1,%2,%3}, {%4,%5,%6,%7}, {%8,%9}, {%0,%1,%2,%3};" \
                 : "+f"((d)[0]), "+f"((d)[1]), "+f"((d)[2]), "+f"((d)[3]) \
                 : "r"((a)[0]), "r"((a)[1]), "r"((a)[2]), "r"((a)[3]), "r"(b0), "r"(b1))

// ============================================================
// Prep: fp16 2-split of W_route||W_noise into swizzled 32-k chunk images
// ============================================================
__global__ void prep_w(const float* __restrict__ Wr, const float* __restrict__ Wn) {
    int idx = blockIdx.x * blockDim.x + threadIdx.x;   // 65536: k x n-pairs
    int k = idx >> 6;
    int n = (idx & 63) * 2;

    float x = (n < NE) ? Wr[n * D_MODEL + k] : Wn[(n - NE) * D_MODEL + k];
    float y = (n + 1 < NE) ? Wr[(n + 1) * D_MODEL + k] : Wn[(n + 1 - NE) * D_MODEL + k];

    __half2 h0 = __floats2half2_rn(x, y);
    float2 f0 = __half22float2(h0);
    __half2 h1 = __floats2half2_rn(x - f0.x, y - f0.y);

    int c = k >> 5, kr = k & 31;
    uint32_t off = (uint32_t)kr * 256 + (((uint32_t)(n * 2)) ^ (((uint32_t)(kr & 7)) << 4));
    *(uint32_t*)(g_Bf + (((size_t)(c * 2 + 0)) << 13) + off) = reinterpret_cast<uint32_t&>(h0);
    *(uint32_t*)(g_Bf + (((size_t)(c * 2 + 1)) << 13) + off) = reinterpret_cast<uint32_t&>(h1);
}

// ============================================================
// Fused split-fp16 HMMA GEMM + noisy top-2 router epilogue
// ============================================================
__device__ __forceinline__ void split_pack8(float4 a, float4 b, uint4& s0, uint4& s1) {
    __half2 p0 = __floats2half2_rn(a.x, a.y);
    __half2 p1 = __floats2half2_rn(a.z, a.w);
    __half2 p2 = __floats2half2_rn(b.x, b.y);
    __half2 p3 = __floats2half2_rn(b.z, b.w);
    float2 f0 = __half22float2(p0), f1 = __half22float2(p1);
    float2 f2 = __half22float2(p2), f3 = __half22float2(p3);
    __half2 q0 = __floats2half2_rn(a.x - f0.x, a.y - f0.y);
    __half2 q1 = __floats2half2_rn(a.z - f1.x, a.w - f1.y);
    __half2 q2 = __floats2half2_rn(b.x - f2.x, b.y - f2.y);
    __half2 q3 = __floats2half2_rn(b.z - f3.x, b.w - f3.y);
    s0.x = reinterpret_cast<uint32_t&>(p0); s0.y = reinterpret_cast<uint32_t&>(p1);
    s0.z = reinterpret_cast<uint32_t&>(p2); s0.w = reinterpret_cast<uint32_t&>(p3);
    s1.x = reinterpret_cast<uint32_t&>(q0); s1.y = reinterpret_cast<uint32_t&>(q1);
    s1.z = reinterpret_cast<uint32_t&>(q2); s1.w = reinterpret_cast<uint32_t&>(q3);
}

__global__ void __launch_bounds__(256, 1)
moe_mma(const float* __restrict__ A, const float* __restrict__ noise,
        const float* __restrict__ br, const float* __restrict__ bn,
        float* __restrict__ out, int M, int write_idx) {
    extern __shared__ __align__(128) unsigned char smem[];
    __shared__ float bias[NN];
    const uint32_t sb = smem_u32(smem);
    const int tid = threadIdx.x;
    const int w = tid >> 5, l = tid & 31;
    const int m0 = blockIdx.x * BM;

    if (tid < NN) bias[tid] = (tid < NE) ? br[tid] : bn[tid - NE];

    const int wm = (w & 3) * 32;          // warp row base
    const int n0 = (w >> 2) * 64;         // warp col base

    // ldmatrix per-lane precomputes
    const int l16 = l & 15;
    const uint32_t khalf16 = (uint32_t)((l >> 4) << 4);
    // A: 64B rows, swizzle c ^ (((r>>1)&3)<<4)
    const uint32_t Ra   = (uint32_t)(wm + l16) * 64;
    const uint32_t swzl = ((uint32_t)((l16 >> 1) & 3)) << 4;
    // B: 256B rows, swizzle c ^ ((r&7)<<4)
    const uint32_t Rb0 = (uint32_t)l16 * 256;
    const uint32_t rxb = ((uint32_t)(l16 & 7)) << 4;
    const uint32_t cbb = (uint32_t)(n0 * 2) + khalf16;

    // A loader mapping: 2 threads per row, 16 fp32 each
    const int arow = tid >> 1, ahalf = tid & 1;
    const float* aptr = A + (size_t)(m0 + arow) * D_MODEL + ahalf * 16;
    const uint32_t a_st  = (uint32_t)arow * 64;
    const uint32_t aswz  = ((uint32_t)((arow >> 1) & 3)) << 4;

    float acc[2][8][4];
#pragma unroll
    for (int i = 0; i < 2; i++)
#pragma unroll
        for (int j = 0; j < 8; j++)
#pragma unroll
            for (int q = 0; q < 4; q++) acc[i][j][q] = 0.f;

    float4 av[2][4];

    auto ldg_a = [&](int c, int s) {
#pragma unroll
        for (int i = 0; i < 4; i++) av[s][i] = *(const float4*)(aptr + c * BK + i * 4);
    };
    auto cp_b = [&](int c, int stg) {
        const unsigned char* src = g_Bf + ((size_t)c << 14);
        uint32_t dst = sb + SM_B_OFF + (uint32_t)stg * BBYTES;
#pragma unroll
        for (int j = 0; j < 4; j++) {
            uint32_t o = (uint32_t)tid * 16 + (uint32_t)j * 4096;
            CP16(dst + o, src + o);
        }
        CP_COMMIT();
    };
    auto sts_a = [&](int s, int stg) {
        unsigned char* b0 = smem + (uint32_t)stg * ABYTES;
#pragma unroll
        for (int g = 0; g < 2; g++) {
            uint4 s0, s1;
            split_pack8(av[s][2 * g], av[s][2 * g + 1], s0, s1);
            uint32_t phys = a_st + (((uint32_t)(ahalf * 32 + g * 16)) ^ aswz);
            *(uint4*)(b0 + phys) = s0;
            *(uint4*)(b0 + 8192 + phys) = s1;
        }
    };

    // ---- prologue ----
    cp_b(0, 0);
    cp_b(1, 1);
    ldg_a(0, 0);
    ldg_a(1, 1);
    sts_a(0, 0);

    // ---- mainloop: one barrier per chunk ----
    for (int c = 0; c < NCH; c++) {
        if (c + 2 < NCH) {
            cp_b(c + 2, (c + 2) & 3);
            ldg_a(c + 2, c & 1);
        }
        if (c + 1 < NCH) sts_a((c + 1) & 1, (c + 1) % 3);

        if (c + 2 < NCH)      asm volatile("cp.async.wait_group 2;");
        else if (c + 1 < NCH) asm volatile("cp.async.wait_group 1;");
        else                  asm volatile("cp.async.wait_group 0;");
        __syncthreads();

        uint32_t Ab = sb + (uint32_t)(c % 3) * ABYTES;
        uint32_t Bb = sb + SM_B_OFF + (uint32_t)(c & 3) * BBYTES;
#pragma unroll
        for (int ks = 0; ks < 2; ks++) {
            uint32_t ca = ((uint32_t)(ks * 32) + khalf16) ^ swzl;
            uint32_t a0f[2][4], a1f[2][4];
            LDSM4(a0f[0], Ab + Ra + ca);
            LDSM4(a0f[1], Ab + Ra + 1024 + ca);
            LDSM4(a1f[0], Ab + 8192 + Ra + ca);
            LDSM4(a1f[1], Ab + 8192 + Ra + 1024 + ca);

            uint32_t Rb = Rb0 + (uint32_t)ks * 4096;
            uint32_t b0f[4][4], b1f[4][4];
#pragma unroll
            for (int nt = 0; nt < 4; nt++) {
                uint32_t cc = (cbb + (uint32_t)(nt * 32)) ^ rxb;
                LDSM4T(b0f[nt], Bb + Rb + cc);
                LDSM4T(b1f[nt], Bb + 8192 + Rb + cc);
            }
#pragma unroll
            for (int mt = 0; mt < 2; mt++)
#pragma unroll
                for (int nt = 0; nt < 4; nt++) {
                    MMA16816(acc[mt][2 * nt],     a0f[mt], b0f[nt][0], b0f[nt][1]);
                    MMA16816(acc[mt][2 * nt + 1], a0f[mt], b0f[nt][2], b0f[nt][3]);
                    MMA16816(acc[mt][2 * nt],     a0f[mt], b1f[nt][0], b1f[nt][1]);
                    MMA16816(acc[mt][2 * nt + 1], a0f[mt], b1f[nt][2], b1f[nt][3]);
                    MMA16816(acc[mt][2 * nt],     a1f[mt], b0f[nt][0], b0f[nt][1]);
                    MMA16816(acc[mt][2 * nt + 1], a1f[mt], b0f[nt][2], b0f[nt][3]);
                }
        }
    }
    __syncthreads();   // protect smem reuse for C

    // ---- epilogue: accs -> SMEM C [128][CSTRIDE] ----
    float* C = (float*)smem;
    {
        int r0 = wm + (l >> 2);
        int cb = n0 + (l & 3) * 2;
#pragma unroll
        for (int mt = 0; mt < 2; mt++)
#pragma unroll
            for (int j = 0; j < 8; j++) {
                int rr = r0 + mt * 16;
                int cc = cb + j * 8;
                *(float2*)(C + rr * CSTRIDE + cc)       = *(float2*)&acc[mt][j][0];
                *(float2*)(C + (rr + 8) * CSTRIDE + cc) = *(float2*)&acc[mt][j][2];
            }
    }
    __syncthreads();

    if (tid < BM) {
        const int token = m0 + tid;
        const float* crow = C + tid * CSTRIDE;
        const float* nrow = noise + (size_t)token * NE;
        float nz[NE];
#pragma unroll
        for (int q = 0; q < NE / 4; q++) *(float4*)(nz + q * 4) = *(const float4*)(nrow + q * 4);

        float v1 = -1e30f, v2 = -1e30f;
        int i1 = 0, i2 = 0;
#pragma unroll 8
        for (int e = 0; e < NE; e++) {
            float rl  = crow[e] + bias[e];
            float nlg = crow[NE + e] + bias[NE + e];
            float sp  = fmaxf(nlg, 0.f) + log1pf(expf(-fabsf(nlg)));
            float z   = rl + nz[e] * sp;
            if (z > v1)      { v2 = v1; i2 = i1; v1 = z; i1 = e; }
            else if (z > v2) { v2 = z; i2 = e; }
        }

        float ex  = expf(v2 - v1);
        float inv = 1.f / (1.f + ex);
        float p1 = inv, p2 = ex * inv;

        float* orow = out + (size_t)token * NE;
        float4 zf = make_float4(0.f, 0.f, 0.f, 0.f);
#pragma unroll
        for (int q = 0; q < NE / 4; q++) *(float4*)(orow + q * 4) = zf;
        orow[i1] = p1;
        orow[i2] = p2;

        if (write_idx) {
            float2 iv = make_float2((float)i1, (float)i2);
            *(float2*)(out + (size_t)M * NE + (size_t)token * 2) = iv;
        }
    }
}

// ============================================================
extern "C" void kernel_launch(void* const* d_in, const int* in_sizes, int n_in,
                              void* d_out, int out_size) {
    const float* mh    = (const float*)d_in[0];
    const float* noise = (const float*)d_in[1];
    const float* Wr    = (const float*)d_in[2];
    const float* br    = (const float*)d_in[3];
    const float* Wn    = (const float*)d_in[4];
    const float* bn    = (const float*)d_in[5];
    float* out = (float*)d_out;

    int M = in_sizes[0] / D_MODEL;   // 32768

    cudaFuncSetAttribute(moe_mma, cudaFuncAttributeMaxDynamicSharedMemorySize, SMEM_BYTES);

    prep_w<<<(D_MODEL * NN / 2) / 256, 256>>>(Wr, Wn);

    int write_idx = (out_size >= M * NE + M * 2) ? 1 : 0;
    moe_mma<<<M / BM, 256, SMEM_BYTES>>>(mh, noise, br, bn, out, M, write_idx);
}

// round 6
// speedup vs baseline: 1.8214x; 1.8214x over previous
#include <cuda_runtime.h>
#include <cuda_fp16.h>
#include <cstdint>

#define D_MODEL 1024
#define NE 64
#define NN 128
#define BM 128
#define BK 64               // fp32 K per chunk
#define NCH (D_MODEL / BK)  // 16
#define SMEM_BYTES 131072   // A: [2buf][2split][16KB] @0, B: [2buf][2split][16KB] @65536
#define CSTRIDE 132

// pre-split, pre-swizzled weights: [split][chunk] 16KB images
__device__ __align__(128) unsigned char g_Bf[2 * NCH * 16384];

// swizzle: 256B rows, XOR col bits[4:6] with row&7
#define SWZB(r, c) ((r) * 256 + ((c) ^ (((r) & 7) << 4)))

__device__ __forceinline__ uint32_t smem_u32(const void* p) {
    uint32_t a;
    asm("{ .reg .u64 t; cvta.to.shared.u64 t, %1; cvt.u32.u64 %0, t; }" : "=r"(a) : "l"(p));
    return a;
}
#define CP16(dst, src) asm volatile("cp.async.ca.shared.global [%0], [%1], 16;" :: "r"(dst), "l"(src))
#define CP_COMMIT()    asm volatile("cp.async.commit_group;")
#define CP_WAIT0()     asm volatile("cp.async.wait_group 0;")

#define LDSM4(r, p) \
    asm volatile("ldmatrix.sync.aligned.m8n8.x4.shared.b16 {%0,%1,%2,%3}, [%4];" \
                 : "=r"((r)[0]), "=r"((r)[1]), "=r"((r)[2]), "=r"((r)[3]) : "r"(p))
#define LDSM4T(r, p) \
    asm volatile("ldmatrix.sync.aligned.m8n8.x4.trans.shared.b16 {%0,%1,%2,%3}, [%4];" \
                 : "=r"((r)[0]), "=r"((r)[1]), "=r"((r)[2]), "=r"((r)[3]) : "r"(p))
#define MMA16816(d, a, b0, b1) \
    asm volatile("mma.sync.aligned.m16n8k16.row.col.f32.f16.f16.f32 " \
                 "{%0,%1,%2,%3}, {%4,%5,%6,%7}, {%8,%9}, {%0,%1,%2,%3};" \
                 : "+f"((d)[0]), "+f"((d)[1]), "+f"((d)[2]), "+f"((d)[3]) \
                 : "r"((a)[0]), "r"((a)[1]), "r"((a)[2]), "r"((a)[3]), "r"(b0), "r"(b1))

// ============================================================
// Prep: fp16 2-split of W_route||W_noise into swizzled k-chunk images
// ============================================================
__global__ void prep_w(const float* __restrict__ Wr, const float* __restrict__ Wn) {
    int idx = blockIdx.x * blockDim.x + threadIdx.x;   // 65536: k x n-pairs
    int k = idx >> 6;
    int n = (idx & 63) * 2;

    float x = (n < NE) ? Wr[n * D_MODEL + k] : Wn[(n - NE) * D_MODEL + k];
    float y = (n + 1 < NE) ? Wr[(n + 1) * D_MODEL + k] : Wn[(n + 1 - NE) * D_MODEL + k];

    __half2 h0 = __floats2half2_rn(x, y);
    float2 f0 = __half22float2(h0);
    __half2 h1 = __floats2half2_rn(x - f0.x, y - f0.y);

    int c = k >> 6, kr = k & 63;
    uint32_t off = SWZB(kr, n * 2);
    *(uint32_t*)(g_Bf + ((size_t)c << 14) + off) = reinterpret_cast<uint32_t&>(h0);
    *(uint32_t*)(g_Bf + (((size_t)(NCH + c)) << 14) + off) = reinterpret_cast<uint32_t&>(h1);
}

// ============================================================
// Fused split-fp16 HMMA GEMM + noisy top-2 router epilogue
// ============================================================
__device__ __forceinline__ void split_pack8(float4 a, float4 b, uint4& s0, uint4& s1) {
    __half2 p0 = __floats2half2_rn(a.x, a.y);
    __half2 p1 = __floats2half2_rn(a.z, a.w);
    __half2 p2 = __floats2half2_rn(b.x, b.y);
    __half2 p3 = __floats2half2_rn(b.z, b.w);
    float2 f0 = __half22float2(p0), f1 = __half22float2(p1);
    float2 f2 = __half22float2(p2), f3 = __half22float2(p3);
    __half2 q0 = __floats2half2_rn(a.x - f0.x, a.y - f0.y);
    __half2 q1 = __floats2half2_rn(a.z - f1.x, a.w - f1.y);
    __half2 q2 = __floats2half2_rn(b.x - f2.x, b.y - f2.y);
    __half2 q3 = __floats2half2_rn(b.z - f3.x, b.w - f3.y);
    s0.x = reinterpret_cast<uint32_t&>(p0); s0.y = reinterpret_cast<uint32_t&>(p1);
    s0.z = reinterpret_cast<uint32_t&>(p2); s0.w = reinterpret_cast<uint32_t&>(p3);
    s1.x = reinterpret_cast<uint32_t&>(q0); s1.y = reinterpret_cast<uint32_t&>(q1);
    s1.z = reinterpret_cast<uint32_t&>(q2); s1.w = reinterpret_cast<uint32_t&>(q3);
}

__global__ void __launch_bounds__(256, 1)
moe_mma(const float* __restrict__ A, const float* __restrict__ noise,
        const float* __restrict__ br, const float* __restrict__ bn,
        float* __restrict__ out, int M, int write_idx) {
    extern __shared__ __align__(128) unsigned char smem[];
    __shared__ float bias[NN];
    const uint32_t sb = smem_u32(smem);
    const int tid = threadIdx.x;
    const int w = tid >> 5, l = tid & 31;
    const int m0 = blockIdx.x * BM;

    if (tid < NN) bias[tid] = (tid < NE) ? br[tid] : bn[tid - NE];

    const int wm = (w & 3) * 32;          // warp row base
    const int n0 = (w >> 2) * 64;         // warp col base

    // ldmatrix per-lane precomputes
    const int l16 = l & 15;
    const uint32_t khalf16 = (uint32_t)((l >> 4) << 4);
    const uint32_t Ra  = (uint32_t)(wm + l16) * 128;       // A row byte (mt=0)
    const uint32_t rxa = ((uint32_t)((wm + l16) & 7)) << 4;
    const uint32_t Rb0 = (uint32_t)l16 * 256;              // B row byte (ks=0)
    const uint32_t rxb = ((uint32_t)(l16 & 7)) << 4;
    const uint32_t cbb = (uint32_t)(n0 * 2) + khalf16;     // B col byte base

    // A loader mapping: 2 threads per row, 32 fp32 each
    const int arow = tid >> 1, ahalf = tid & 1;
    const float* aptr = A + (size_t)(m0 + arow) * D_MODEL + ahalf * 32;
    const uint32_t arow_rx = ((uint32_t)(arow & 7)) << 4;
    const uint32_t a_st_row = (uint32_t)arow * 128;

    float acc[2][8][4];
#pragma unroll
    for (int i = 0; i < 2; i++)
#pragma unroll
        for (int j = 0; j < 8; j++)
#pragma unroll
            for (int q = 0; q < 4; q++) acc[i][j][q] = 0.f;

    float4 av[8];

    auto ldg_a = [&](int c) {
#pragma unroll
        for (int i = 0; i < 8; i++) av[i] = *(const float4*)(aptr + c * BK + i * 4);
    };
    auto cp_b = [&](int c, int buf) {
#pragma unroll
        for (int s = 0; s < 2; s++) {
            const unsigned char* src = g_Bf + (((size_t)(s * NCH + c)) << 14);
            uint32_t dst = sb + 65536 + buf * 32768 + s * 16384;
#pragma unroll
            for (int j = 0; j < 4; j++) {
                uint32_t o = (uint32_t)(tid + j * 256) * 16;
                CP16(dst + o, src + o);
            }
        }
        CP_COMMIT();
    };
    auto sts_a = [&](int buf) {
        unsigned char* base0 = smem + buf * 32768;
        unsigned char* base1 = base0 + 16384;
#pragma unroll
        for (int q = 0; q < 4; q++) {
            uint4 s0, s1;
            split_pack8(av[2 * q], av[2 * q + 1], s0, s1);
            uint32_t phys = a_st_row + (((uint32_t)(ahalf * 64 + q * 16)) ^ arow_rx);
            *(uint4*)(base0 + phys) = s0;
            *(uint4*)(base1 + phys) = s1;
        }
    };

    // prologue
    ldg_a(0);
    cp_b(0, 0);
    sts_a(0);
    CP_WAIT0();
    __syncthreads();

    for (int c = 0; c < NCH; c++) {
        int buf = c & 1;
        if (c + 1 < NCH) { ldg_a(c + 1); cp_b(c + 1, buf ^ 1); }

        uint32_t Ab = sb + buf * 32768;
        uint32_t Bb = sb + 65536 + buf * 32768;
#pragma unroll
        for (int ks = 0; ks < 4; ks++) {
            uint32_t ca = ((uint32_t)(ks * 32) + khalf16) ^ rxa;
            uint32_t a0f[2][4], a1f[2][4];
            LDSM4(a0f[0], Ab + Ra + ca);
            LDSM4(a0f[1], Ab + Ra + 2048 + ca);
            LDSM4(a1f[0], Ab + 16384 + Ra + ca);
            LDSM4(a1f[1], Ab + 16384 + Ra + 2048 + ca);

            uint32_t Rb = Rb0 + (uint32_t)ks * 4096;
            uint32_t b0f[4][4], b1f[4][4];
#pragma unroll
            for (int nt = 0; nt < 4; nt++) {
                uint32_t cc = (cbb + (uint32_t)(nt * 32)) ^ rxb;
                LDSM4T(b0f[nt], Bb + Rb + cc);
                LDSM4T(b1f[nt], Bb + 16384 + Rb + cc);
            }
            // term-major ordering: consecutive MMAs always hit different accs,
            // same acc recurs only after 16 MMAs -> RAW latency fully hidden.
#pragma unroll
            for (int mt = 0; mt < 2; mt++)
#pragma unroll
                for (int nt = 0; nt < 4; nt++) {
                    MMA16816(acc[mt][2 * nt],     a0f[mt], b0f[nt][0], b0f[nt][1]);
                    MMA16816(acc[mt][2 * nt + 1], a0f[mt], b0f[nt][2], b0f[nt][3]);
                }
#pragma unroll
            for (int mt = 0; mt < 2; mt++)
#pragma unroll
                for (int nt = 0; nt < 4; nt++) {
                    MMA16816(acc[mt][2 * nt],     a0f[mt], b1f[nt][0], b1f[nt][1]);
                    MMA16816(acc[mt][2 * nt + 1], a0f[mt], b1f[nt][2], b1f[nt][3]);
                }
#pragma unroll
            for (int mt = 0; mt < 2; mt++)
#pragma unroll
                for (int nt = 0; nt < 4; nt++) {
                    MMA16816(acc[mt][2 * nt],     a1f[mt], b0f[nt][0], b0f[nt][1]);
                    MMA16816(acc[mt][2 * nt + 1], a1f[mt], b0f[nt][2], b0f[nt][3]);
                }
        }

        if (c + 1 < NCH) { sts_a(buf ^ 1); CP_WAIT0(); }
        __syncthreads();
    }

    // ---- epilogue: accs -> SMEM C [128][CSTRIDE] ----
    float* C = (float*)smem;
    {
        int r0 = wm + (l >> 2);
        int cb = n0 + (l & 3) * 2;
#pragma unroll
        for (int mt = 0; mt < 2; mt++)
#pragma unroll
            for (int j = 0; j < 8; j++) {
                int rr = r0 + mt * 16;
                int cc = cb + j * 8;
                *(float2*)(C + rr * CSTRIDE + cc)       = *(float2*)&acc[mt][j][0];
                *(float2*)(C + (rr + 8) * CSTRIDE + cc) = *(float2*)&acc[mt][j][2];
            }
    }
    __syncthreads();

    if (tid < BM) {
        const int token = m0 + tid;
        const float* crow = C + tid * CSTRIDE;
        const float* nrow = noise + (size_t)token * NE;
        float nz[NE];
#pragma unroll
        for (int q = 0; q < NE / 4; q++) *(float4*)(nz + q * 4) = *(const float4*)(nrow + q * 4);

        float v1 = -1e30f, v2 = -1e30f;
        int i1 = 0, i2 = 0;
#pragma unroll 8
        for (int e = 0; e < NE; e++) {
            float rl  = crow[e] + bias[e];
            float nlg = crow[NE + e] + bias[NE + e];
            float sp  = fmaxf(nlg, 0.f) + log1pf(expf(-fabsf(nlg)));
            float z   = rl + nz[e] * sp;
            if (z > v1)      { v2 = v1; i2 = i1; v1 = z; i1 = e; }
            else if (z > v2) { v2 = z; i2 = e; }
        }

        float ex  = expf(v2 - v1);
        float inv = 1.f / (1.f + ex);
        float p1 = inv, p2 = ex * inv;

        float* orow = out + (size_t)token * NE;
        float4 zf = make_float4(0.f, 0.f, 0.f, 0.f);
#pragma unroll
        for (int q = 0; q < NE / 4; q++) *(float4*)(orow + q * 4) = zf;
        orow[i1] = p1;
        orow[i2] = p2;

        if (write_idx) {
            float2 iv = make_float2((float)i1, (float)i2);
            *(float2*)(out + (size_t)M * NE + (size_t)token * 2) = iv;
        }
    }
}

// ============================================================
extern "C" void kernel_launch(void* const* d_in, const int* in_sizes, int n_in,
                              void* d_out, int out_size) {
    const float* mh    = (const float*)d_in[0];
    const float* noise = (const float*)d_in[1];
    const float* Wr    = (const float*)d_in[2];
    const float* br    = (const float*)d_in[3];
    const float* Wn    = (const float*)d_in[4];
    const float* bn    = (const float*)d_in[5];
    float* out = (float*)d_out;

    int M = in_sizes[0] / D_MODEL;   // 32768

    cudaFuncSetAttribute(moe_mma, cudaFuncAttributeMaxDynamicSharedMemorySize, SMEM_BYTES);

    prep_w<<<(D_MODEL * NN / 2) / 256, 256>>>(Wr, Wn);

    int write_idx = (out_size >= M * NE + M * 2) ? 1 : 0;
    moe_mma<<<M / BM, 256, SMEM_BYTES>>>(mh, noise, br, bn, out, M, write_idx);
}

// round 7
// speedup vs baseline: 1.8402x; 1.0103x over previous
#include <cuda_runtime.h>
#include <cuda_fp16.h>
#include <cstdint>

#define D_MODEL 1024
#define NE 64
#define NN 128
#define BM 128
#define BK 64               // fp32 K per chunk
#define NCH (D_MODEL / BK)  // 16
#define NTHREADS 512
#define SMEM_BYTES 131072   // A: [2buf][2split][16KB] @0, B: [2buf][2split][16KB] @65536
#define CSTRIDE 132

// pre-split, pre-swizzled weights: [split][chunk] 16KB images
__device__ __align__(128) unsigned char g_Bf[2 * NCH * 16384];

// swizzle: 256B rows, XOR col bits[4:6] with row&7
#define SWZB(r, c) ((r) * 256 + ((c) ^ (((r) & 7) << 4)))

__device__ __forceinline__ uint32_t smem_u32(const void* p) {
    uint32_t a;
    asm("{ .reg .u64 t; cvta.to.shared.u64 t, %1; cvt.u32.u64 %0, t; }" : "=r"(a) : "l"(p));
    return a;
}
#define CP16(dst, src) asm volatile("cp.async.ca.shared.global [%0], [%1], 16;" :: "r"(dst), "l"(src))
#define CP_COMMIT()    asm volatile("cp.async.commit_group;")
#define CP_WAIT0()     asm volatile("cp.async.wait_group 0;")

#define LDSM4(r, p) \
    asm volatile("ldmatrix.sync.aligned.m8n8.x4.shared.b16 {%0,%1,%2,%3}, [%4];" \
                 : "=r"((r)[0]), "=r"((r)[1]), "=r"((r)[2]), "=r"((r)[3]) : "r"(p))
#define LDSM4T(r, p) \
    asm volatile("ldmatrix.sync.aligned.m8n8.x4.trans.shared.b16 {%0,%1,%2,%3}, [%4];" \
                 : "=r"((r)[0]), "=r"((r)[1]), "=r"((r)[2]), "=r"((r)[3]) : "r"(p))
#define MMA16816(d, a, b0, b1) \
    asm volatile("mma.sync.aligned.m16n8k16.row.col.f32.f16.f16.f32 " \
                 "{%0,%1,%2,%3}, {%4,%5,%6,%7}, {%8,%9}, {%0,%1,%2,%3};" \
                 : "+f"((d)[0]), "+f"((d)[1]), "+f"((d)[2]), "+f"((d)[3]) \
                 : "r"((a)[0]), "r"((a)[1]), "r"((a)[2]), "r"((a)[3]), "r"(b0), "r"(b1))

// ============================================================
// Prep: fp16 2-split of W_route||W_noise into swizzled k-chunk images
// ============================================================
__global__ void prep_w(const float* __restrict__ Wr, const float* __restrict__ Wn) {
    int idx = blockIdx.x * blockDim.x + threadIdx.x;   // 65536: k x n-pairs
    int k = idx >> 6;
    int n = (idx & 63) * 2;

    float x = (n < NE) ? Wr[n * D_MODEL + k] : Wn[(n - NE) * D_MODEL + k];
    float y = (n + 1 < NE) ? Wr[(n + 1) * D_MODEL + k] : Wn[(n + 1 - NE) * D_MODEL + k];

    __half2 h0 = __floats2half2_rn(x, y);
    float2 f0 = __half22float2(h0);
    __half2 h1 = __floats2half2_rn(x - f0.x, y - f0.y);

    int c = k >> 6, kr = k & 63;
    uint32_t off = SWZB(kr, n * 2);
    *(uint32_t*)(g_Bf + ((size_t)c << 14) + off) = reinterpret_cast<uint32_t&>(h0);
    *(uint32_t*)(g_Bf + (((size_t)(NCH + c)) << 14) + off) = reinterpret_cast<uint32_t&>(h1);
}

// ============================================================
// Fused split-fp16 HMMA GEMM + noisy top-2 router epilogue
// 512 threads, 16 warps, warp tile 16x64 (4 warps per SMSP)
// ============================================================
__device__ __forceinline__ void split_pack8(float4 a, float4 b, uint4& s0, uint4& s1) {
    __half2 p0 = __floats2half2_rn(a.x, a.y);
    __half2 p1 = __floats2half2_rn(a.z, a.w);
    __half2 p2 = __floats2half2_rn(b.x, b.y);
    __half2 p3 = __floats2half2_rn(b.z, b.w);
    float2 f0 = __half22float2(p0), f1 = __half22float2(p1);
    float2 f2 = __half22float2(p2), f3 = __half22float2(p3);
    __half2 q0 = __floats2half2_rn(a.x - f0.x, a.y - f0.y);
    __half2 q1 = __floats2half2_rn(a.z - f1.x, a.w - f1.y);
    __half2 q2 = __floats2half2_rn(b.x - f2.x, b.y - f2.y);
    __half2 q3 = __floats2half2_rn(b.z - f3.x, b.w - f3.y);
    s0.x = reinterpret_cast<uint32_t&>(p0); s0.y = reinterpret_cast<uint32_t&>(p1);
    s0.z = reinterpret_cast<uint32_t&>(p2); s0.w = reinterpret_cast<uint32_t&>(p3);
    s1.x = reinterpret_cast<uint32_t&>(q0); s1.y = reinterpret_cast<uint32_t&>(q1);
    s1.z = reinterpret_cast<uint32_t&>(q2); s1.w = reinterpret_cast<uint32_t&>(q3);
}

__global__ void __launch_bounds__(NTHREADS, 1)
moe_mma(const float* __restrict__ A, const float* __restrict__ noise,
        const float* __restrict__ br, const float* __restrict__ bn,
        float* __restrict__ out, int M, int write_idx) {
    extern __shared__ __align__(128) unsigned char smem[];
    __shared__ float bias[NN];
    const uint32_t sb = smem_u32(smem);
    const int tid = threadIdx.x;
    const int w = tid >> 5, l = tid & 31;
    const int m0 = blockIdx.x * BM;

    if (tid < NN) bias[tid] = (tid < NE) ? br[tid] : bn[tid - NE];

    const int wm = (w & 7) * 16;          // warp row base (16 rows)
    const int n0 = (w >> 3) * 64;         // warp col base

    // ldmatrix per-lane precomputes
    const int l16 = l & 15;
    const uint32_t khalf16 = (uint32_t)((l >> 4) << 4);
    const uint32_t Ra  = (uint32_t)(wm + l16) * 128;       // A row byte
    const uint32_t rxa = ((uint32_t)(l16 & 7)) << 4;       // (wm+l16)&7 == l16&7
    const uint32_t Rb0 = (uint32_t)l16 * 256;              // B row byte (ks=0)
    const uint32_t rxb = ((uint32_t)(l16 & 7)) << 4;
    const uint32_t cbb = (uint32_t)(n0 * 2) + khalf16;     // B col byte base

    // A loader mapping: 4 threads per row, 16 fp32 each
    const int arow = tid >> 2, aq = tid & 3;
    const float* aptr = A + (size_t)(m0 + arow) * D_MODEL + aq * 16;
    const uint32_t arow_rx = ((uint32_t)(arow & 7)) << 4;
    const uint32_t a_st_row = (uint32_t)arow * 128;

    float acc[8][4];
#pragma unroll
    for (int j = 0; j < 8; j++)
#pragma unroll
        for (int q = 0; q < 4; q++) acc[j][q] = 0.f;

    float4 av[4];

    auto ldg_a = [&](int c) {
#pragma unroll
        for (int i = 0; i < 4; i++) av[i] = *(const float4*)(aptr + c * BK + i * 4);
    };
    auto cp_b = [&](int c, int buf) {
#pragma unroll
        for (int s = 0; s < 2; s++) {
            const unsigned char* src = g_Bf + (((size_t)(s * NCH + c)) << 14);
            uint32_t dst = sb + 65536 + buf * 32768 + s * 16384;
#pragma unroll
            for (int j = 0; j < 2; j++) {
                uint32_t o = (uint32_t)(tid + j * NTHREADS) * 16;
                CP16(dst + o, src + o);
            }
        }
        CP_COMMIT();
    };
    auto sts_a = [&](int buf) {
        unsigned char* base0 = smem + buf * 32768;
        unsigned char* base1 = base0 + 16384;
#pragma unroll
        for (int g = 0; g < 2; g++) {
            uint4 s0, s1;
            split_pack8(av[2 * g], av[2 * g + 1], s0, s1);
            uint32_t phys = a_st_row + (((uint32_t)(aq * 32 + g * 16)) ^ arow_rx);
            *(uint4*)(base0 + phys) = s0;
            *(uint4*)(base1 + phys) = s1;
        }
    };

    // prologue
    ldg_a(0);
    cp_b(0, 0);
    sts_a(0);
    CP_WAIT0();
    __syncthreads();

    for (int c = 0; c < NCH; c++) {
        int buf = c & 1;
        if (c + 1 < NCH) { ldg_a(c + 1); cp_b(c + 1, buf ^ 1); }

        uint32_t Ab = sb + buf * 32768;
        uint32_t Bb = sb + 65536 + buf * 32768;
#pragma unroll
        for (int ks = 0; ks < 4; ks++) {
            uint32_t ca = ((uint32_t)(ks * 32) + khalf16) ^ rxa;
            uint32_t a0f[4], a1f[4];
            LDSM4(a0f, Ab + Ra + ca);
            LDSM4(a1f, Ab + 16384 + Ra + ca);

            uint32_t Rb = Rb0 + (uint32_t)ks * 4096;
            uint32_t b0f[4][4], b1f[4][4];
#pragma unroll
            for (int nt = 0; nt < 4; nt++) {
                uint32_t cc = (cbb + (uint32_t)(nt * 32)) ^ rxb;
                LDSM4T(b0f[nt], Bb + Rb + cc);
                LDSM4T(b1f[nt], Bb + 16384 + Rb + cc);
            }
#pragma unroll
            for (int nt = 0; nt < 4; nt++) {
                MMA16816(acc[2 * nt],     a0f, b0f[nt][0], b0f[nt][1]);
                MMA16816(acc[2 * nt + 1], a0f, b0f[nt][2], b0f[nt][3]);
            }
#pragma unroll
            for (int nt = 0; nt < 4; nt++) {
                MMA16816(acc[2 * nt],     a0f, b1f[nt][0], b1f[nt][1]);
                MMA16816(acc[2 * nt + 1], a0f, b1f[nt][2], b1f[nt][3]);
            }
#pragma unroll
            for (int nt = 0; nt < 4; nt++) {
                MMA16816(acc[2 * nt],     a1f, b0f[nt][0], b0f[nt][1]);
                MMA16816(acc[2 * nt + 1], a1f, b0f[nt][2], b0f[nt][3]);
            }
        }

        if (c + 1 < NCH) { sts_a(buf ^ 1); CP_WAIT0(); }
        __syncthreads();
    }

    // ---- epilogue: accs -> SMEM C [128][CSTRIDE] ----
    float* C = (float*)smem;
    {
        int r0 = wm + (l >> 2);
        int cb = n0 + (l & 3) * 2;
#pragma unroll
        for (int j = 0; j < 8; j++) {
            int cc = cb + j * 8;
            *(float2*)(C + r0 * CSTRIDE + cc)       = *(float2*)&acc[j][0];
            *(float2*)(C + (r0 + 8) * CSTRIDE + cc) = *(float2*)&acc[j][2];
        }
    }
    __syncthreads();

    if (tid < BM) {
        const int token = m0 + tid;
        const float* crow = C + tid * CSTRIDE;
        const float* nrow = noise + (size_t)token * NE;
        float nz[NE];
#pragma unroll
        for (int q = 0; q < NE / 4; q++) *(float4*)(nz + q * 4) = *(const float4*)(nrow + q * 4);

        float v1 = -1e30f, v2 = -1e30f;
        int i1 = 0, i2 = 0;
#pragma unroll 8
        for (int e = 0; e < NE; e++) {
            float rl  = crow[e] + bias[e];
            float nlg = crow[NE + e] + bias[NE + e];
            float sp  = fmaxf(nlg, 0.f) + log1pf(expf(-fabsf(nlg)));
            float z   = rl + nz[e] * sp;
            if (z > v1)      { v2 = v1; i2 = i1; v1 = z; i1 = e; }
            else if (z > v2) { v2 = z; i2 = e; }
        }

        float ex  = expf(v2 - v1);
        float inv = 1.f / (1.f + ex);
        float p1 = inv, p2 = ex * inv;

        float* orow = out + (size_t)token * NE;
        float4 zf = make_float4(0.f, 0.f, 0.f, 0.f);
#pragma unroll
        for (int q = 0; q < NE / 4; q++) *(float4*)(orow + q * 4) = zf;
        orow[i1] = p1;
        orow[i2] = p2;

        if (write_idx) {
            float2 iv = make_float2((float)i1, (float)i2);
            *(float2*)(out + (size_t)M * NE + (size_t)token * 2) = iv;
        }
    }
}

// ============================================================
extern "C" void kernel_launch(void* const* d_in, const int* in_sizes, int n_in,
                              void* d_out, int out_size) {
    const float* mh    = (const float*)d_in[0];
    const float* noise = (const float*)d_in[1];
    const float* Wr    = (const float*)d_in[2];
    const float* br    = (const float*)d_in[3];
    const float* Wn    = (const float*)d_in[4];
    const float* bn    = (const float*)d_in[5];
    float* out = (float*)d_out;

    int M = in_sizes[0] / D_MODEL;   // 32768

    cudaFuncSetAttribute(moe_mma, cudaFuncAttributeMaxDynamicSharedMemorySize, SMEM_BYTES);

    prep_w<<<(D_MODEL * NN / 2) / 256, 256>>>(Wr, Wn);

    int write_idx = (out_size >= M * NE + M * 2) ? 1 : 0;
    moe_mma<<<M / BM, NTHREADS, SMEM_BYTES>>>(mh, noise, br, bn, out, M, write_idx);
}